// round 11
// baseline (speedup 1.0000x reference)
#include <cuda_runtime.h>
#include <math.h>

#define H_FIXED 16
#define K_FIXED 5
#define TPB 256
#define R_ROWS 16
#define GS 2                      // row-groups per block (32 rows)
#define WIN 1056                  // window floats: TPB*4 + R_ROWS*GS = 1056
// Block window: win[m] = revsc[w0 + m], revsc[q] = scores[2S - q]
//   w0 = S - 30 - i0 + jbase
// Thread (tid) group t in {0,1}: w_t[k] = win[16*(1-t) + 4*tid + k], k=0..19
//   row r of group t: out[h, i0 + 16t + r, j..j+3] = w_t[15-r .. 18-r]
// All SMEM reads are word-offset = multiple of 4 -> aligned LDS.128, conflict-free.

__global__ void __launch_bounds__(TPB)
tisa_fused_kernel(float4* __restrict__ out,
                  const float* __restrict__ koff,
                  const float* __restrict__ kwid,
                  const float* __restrict__ kamp,
                  int S) {
    __shared__ __align__(16) float win[WIN + 4];

    const int h     = blockIdx.z;
    const int i0    = blockIdx.y * (R_ROWS * GS);
    const int jbase = blockIdx.x * (TPB * 4);
    const int tid   = threadIdx.x;
    const int S4    = S >> 2;

    // ---- Phase 1: compute this block's revsc window into SMEM ----
    // Hoist the 15 per-head params into registers (uniform broadcast loads).
    float po[K_FIXED], pw[K_FIXED], pa[K_FIXED];
#pragma unroll
    for (int k = 0; k < K_FIXED; k++) {
        po[k] = __ldg(koff + k * H_FIXED + h);
        pw[k] = fabsf(__ldg(kwid + k * H_FIXED + h));
        pa[k] = __ldg(kamp + k * H_FIXED + h);
    }
    const int w0 = S - 30 - i0 + jbase;
    for (int m = tid; m < WIN; m += TPB) {
        float rel = (float)(S - (w0 + m));   // rel offset for revsc[w0+m]
        float sum = 0.0f;
#pragma unroll
        for (int k = 0; k < K_FIXED; k++) {
            float d = po[k] - rel;
            sum += pa[k] * __expf(-pw[k] * d * d);
        }
        win[m] = sum;
    }
    __syncthreads();

    const int j4 = blockIdx.x * TPB + tid;   // float4 column index
    if (j4 >= S4) return;

    const float4* __restrict__ W4 = (const float4*)win;

    // ---- Phase 2: register window + streaming stores ----
    // Group 0 window: words [16 + 4*tid .. +19]  -> chunks W4[4 + tid + c]
    float w[20];
#pragma unroll
    for (int c = 0; c < 5; c++) {
        float4 t4 = W4[4 + tid + c];
        w[c * 4 + 0] = t4.x;
        w[c * 4 + 1] = t4.y;
        w[c * 4 + 2] = t4.z;
        w[c * 4 + 3] = t4.w;
    }

    float4* __restrict__ dst = out + ((size_t)h * S + i0) * (size_t)S4 + j4;

#pragma unroll
    for (int t = 0; t < GS; t++) {
        // Prefetch group t+1's new low chunk before this group's stores
        float4 nl;
        if (t < GS - 1) nl = W4[tid];        // words [4*tid .. +3]

#pragma unroll
        for (int r = 0; r < R_ROWS; r++) {
            int k = (R_ROWS - 1) - r;        // 15 - r
            float4 o;
            o.x = w[k + 0];
            o.y = w[k + 1];
            o.z = w[k + 2];
            o.w = w[k + 3];
            __stcs(dst + (size_t)(t * R_ROWS + r) * S4, o);
        }

        if (t < GS - 1) {
            // slide window down 16: old w[0..3] -> w[16..19], new low 16 from nl..
            w[16] = w[0];  w[17] = w[1];  w[18] = w[2];  w[19] = w[3];
            // words [4*tid+4 .. 4*tid+15] are chunks W4[tid+1], W4[tid+2], W4[tid+3]
            float4 a1 = W4[tid + 1];
            float4 a2 = W4[tid + 2];
            float4 a3 = W4[tid + 3];
            w[0]  = nl.x;  w[1]  = nl.y;  w[2]  = nl.z;  w[3]  = nl.w;
            w[4]  = a1.x;  w[5]  = a1.y;  w[6]  = a1.z;  w[7]  = a1.w;
            w[8]  = a2.x;  w[9]  = a2.y;  w[10] = a2.z;  w[11] = a2.w;
            w[12] = a3.x;  w[13] = a3.y;  w[14] = a3.z;  w[15] = a3.w;
        }
    }
}

extern "C" void kernel_launch(void* const* d_in, const int* in_sizes, int n_in,
                              void* d_out, int out_size) {
    // Inputs (metadata order): seq_len (scalar, unused), offsets [K,H],
    // widths [K,H], amplitudes [K,H]
    const float* koff = (const float*)d_in[1];
    const float* kwid = (const float*)d_in[2];
    const float* kamp = (const float*)d_in[3];

    // out_size = H * S * S; H = 16 fixed for this problem
    int S = (int)llround(sqrt((double)out_size / (double)H_FIXED));
    int S4 = S >> 2;

    dim3 grid((S4 + TPB - 1) / TPB, S / (R_ROWS * GS), H_FIXED);
    tisa_fused_kernel<<<grid, TPB>>>((float4*)d_out, koff, kwid, kamp, S);
}

// round 13
// speedup vs baseline: 1.2916x; 1.2916x over previous
#include <cuda_runtime.h>
#include <math.h>

#define H_FIXED 16
#define K_FIXED 5
#define MAX_S 4096
#define L4_OF(S) (2 * (S) + 4)              // per-head padded length (multiple of 4)
#define MAX_L4 (2 * MAX_S + 4)

// 4 phase-shifted copies of the reversed scores table:
//   T[a][h][m] = revsc[h][m + a],  revsc[h][q] = scores[h][2S - q]
// Reading phase a = idx0 & 3 from aligned element (idx0 - a) yields
// revsc[idx0 ...] with 16B-aligned float4 loads for any idx0.
__device__ __align__(16) float g_tab[4 * H_FIXED * MAX_L4];

// Kernel 1: compute revsc[h][q], scatter into the 4 phase copies.
__global__ void tisa_scores_kernel(const float* __restrict__ off,
                                   const float* __restrict__ wid,
                                   const float* __restrict__ amp,
                                   int S) {
    const int L = 2 * S + 1;
    const int total = H_FIXED * L;
    int idx = blockIdx.x * blockDim.x + threadIdx.x;
    if (idx >= total) return;
    int h = idx / L;
    int q = idx - h * L;
    float rel = (float)(S - q);            // revsc[q] = scores[2S - q]
    float sum = 0.0f;
#pragma unroll
    for (int k = 0; k < K_FIXED; k++) {
        float o = off[k * H_FIXED + h];
        float w = fabsf(wid[k * H_FIXED + h]);
        float a = amp[k * H_FIXED + h];
        float d = o - rel;
        sum += a * __expf(-w * d * d);
    }
    const int L4 = L4_OF(S);
#pragma unroll
    for (int a = 0; a < 4; a++) {
        int m = q - a;                      // T[a][h][m] = revsc[h][m + a]
        if (m >= 0)
            g_tab[((size_t)a * H_FIXED + h) * L4 + m] = sum;
    }
}

// Kernel 2: sliding-window pipelined expansion (round-8 proven structure)
// + PDL: prologue overlaps the scores kernel; gate before first table read.
#define R_ROWS 16
#define GS 4
#define TPB 256

__global__ void __launch_bounds__(TPB)
tisa_expand_kernel(float4* __restrict__ out, int S) {
    const int h   = blockIdx.z;
    const int seg = blockIdx.y;
    const int j4  = blockIdx.x * TPB + threadIdx.x;   // float4 column index
    const int S4  = S >> 2;
    const int j = j4 << 2;

    const int g0 = seg * GS;                // first row-group of this segment
    const int i0 = g0 * R_ROWS;

    // Window base for t=0 (lowest source index of group g0)
    const int idx0 = (S + 1) - (i0 + R_ROWS - 1) + j;   // = S - 14 - i0 + j
    const int a = idx0 & 3;                              // uniform across segment
    const int L4 = L4_OF(S);
    const float4* __restrict__ T =
        (const float4*)(g_tab + ((size_t)a * H_FIXED + h) * L4 + (idx0 - a));
    float4* __restrict__ dst = out + ((size_t)h * S + i0) * (size_t)S4 + j4;

    // Wait for the scores kernel (PDL gate). Everything above overlapped it.
    cudaGridDependencySynchronize();

    if (j4 >= S4) return;

    float w[20];
#pragma unroll
    for (int c = 0; c < 5; c++) {           // preload window of group g0
        float4 t4 = __ldg(T + c);
        w[c * 4 + 0] = t4.x;
        w[c * 4 + 1] = t4.y;
        w[c * 4 + 2] = t4.z;
        w[c * 4 + 3] = t4.w;
    }

#pragma unroll
    for (int t = 0; t < GS; t++) {
        // Prefetch next window's 4 new chunks before this group's stores
        float4 n0, n1, n2, n3;
        if (t < GS - 1) {
            const float4* Tn = T - 4 * (t + 1);
            n0 = __ldg(Tn + 0);
            n1 = __ldg(Tn + 1);
            n2 = __ldg(Tn + 2);
            n3 = __ldg(Tn + 3);
        }

        // 16 back-to-back streaming stores for group t
#pragma unroll
        for (int r = 0; r < R_ROWS; r++) {
            int k = (R_ROWS - 1) - r;       // 15 - r
            float4 o;
            o.x = w[k + 0];
            o.y = w[k + 1];
            o.z = w[k + 2];
            o.w = w[k + 3];
            __stcs(dst + (size_t)(t * R_ROWS + r) * S4, o);
        }

        // Slide window down by 16: keep old w[0..3] as new w[16..19]
        if (t < GS - 1) {
            w[16] = w[0];  w[17] = w[1];  w[18] = w[2];  w[19] = w[3];
            w[0]  = n0.x;  w[1]  = n0.y;  w[2]  = n0.z;  w[3]  = n0.w;
            w[4]  = n1.x;  w[5]  = n1.y;  w[6]  = n1.z;  w[7]  = n1.w;
            w[8]  = n2.x;  w[9]  = n2.y;  w[10] = n2.z;  w[11] = n2.w;
            w[12] = n3.x;  w[13] = n3.y;  w[14] = n3.z;  w[15] = n3.w;
        }
    }
}

extern "C" void kernel_launch(void* const* d_in, const int* in_sizes, int n_in,
                              void* d_out, int out_size) {
    // Inputs (metadata order): seq_len (scalar, unused), offsets [K,H],
    // widths [K,H], amplitudes [K,H]
    const float* off = (const float*)d_in[1];
    const float* wid = (const float*)d_in[2];
    const float* amp = (const float*)d_in[3];

    // out_size = H * S * S; H = 16 fixed for this problem
    int S = (int)llround(sqrt((double)out_size / (double)H_FIXED));
    int S4 = S >> 2;

    // Kernel 1: phase-shifted table build
    {
        int total = H_FIXED * (2 * S + 1);
        int threads = 256;
        int blocks = (total + threads - 1) / threads;
        tisa_scores_kernel<<<blocks, threads>>>(off, wid, amp, S);
    }

    // Kernel 2: pipelined expansion, launched with PDL so its prologue
    // overlaps the scores kernel's tail.
    {
        dim3 grid((S4 + TPB - 1) / TPB, S / (R_ROWS * GS), H_FIXED);

        cudaLaunchConfig_t cfg = {};
        cfg.gridDim = grid;
        cfg.blockDim = dim3(TPB, 1, 1);
        cfg.dynamicSmemBytes = 0;
        cfg.stream = 0;
        cudaLaunchAttribute attrs[1];
        attrs[0].id = cudaLaunchAttributeProgrammaticStreamSerialization;
        attrs[0].val.programmaticStreamSerializationAllowed = 1;
        cfg.attrs = attrs;
        cfg.numAttrs = 1;

        cudaError_t e = cudaLaunchKernelEx(&cfg, tisa_expand_kernel,
                                           (float4*)d_out, S);
        if (e != cudaSuccess) {
            // Fallback: plain launch (cudaGridDependencySynchronize is a
            // no-op once upstream work is already serialized).
            cudaGetLastError();
            tisa_expand_kernel<<<grid, TPB>>>((float4*)d_out, S);
        }
    }
}